// round 10
// baseline (speedup 1.0000x reference)
#include <cuda_runtime.h>

// Scratch (no allocations allowed).
#define MAX_MATCH 8192
__device__ int      g_cnt    = 0;
__device__ unsigned g_ticket = 0u;
__device__ int      g_dsts[MAX_MATCH];

__device__ __forceinline__ float leaky(float v) {
    return v >= 0.f ? v : 0.2f * v;
}

// Warp-collective dot (lane reads float4 at 4*lane, stride 128 floats).
__device__ __forceinline__ float warp_dot(const float* __restrict__ row,
                                          const float* __restrict__ wvec,
                                          int D, int lane) {
    float s = 0.f;
    for (int k = 4 * lane; k < D; k += 128) {
        float4 a = *(const float4*)(row + k);
        float4 b = *(const float4*)(wvec + k);
        s += a.x * b.x + a.y * b.y + a.z * b.z + a.w * b.w;
    }
    #pragma unroll
    for (int off = 16; off > 0; off >>= 1)
        s += __shfl_down_sync(0xffffffffu, s, off);
    return s;   // valid on lane 0
}

// Single-thread dot: 32 independent float4 loads -> one DRAM latency.
__device__ float thread_dot(const float* __restrict__ row,
                            const float* __restrict__ wvec, int D) {
    const float4* __restrict__ a = (const float4*)row;
    const float4* __restrict__ b = (const float4*)wvec;
    float acc = 0.f;
    int n4 = D >> 2;
    #pragma unroll 8
    for (int k = 0; k < n4; k++) {
        float4 x = a[k];
        float4 y = b[k];
        acc += x.x * y.x + x.y * y.y + x.z * y.z + x.w * y.w;
    }
    return acc;
}

#define UNB 4u   // int4 units batched per thread per outer iteration (MLP=4)

// ---------------------------------------------------------------------------
// Persistent single-wave fused kernel: batched flat scan (MLP=4), then last
// block (grid-completion ticket) runs the cold epilogue.
// ---------------------------------------------------------------------------
__global__ void __launch_bounds__(256, 8)
gat_fused(const int4* __restrict__ g4, unsigned nPairs, int rem,
          const int2* __restrict__ gall,
          const float* __restrict__ h, const float* __restrict__ W,
          const float* __restrict__ bptr,
          const int* __restrict__ ip, const int* __restrict__ jp,
          int D, float* __restrict__ out) {
    const int t = threadIdx.x;
    const int i = __ldg(ip);
    const unsigned tile   = 256u * UNB;          // units per block per iter
    const unsigned stride = gridDim.x * tile;    // grid advance per iter

    // ---- hot path: batch 4 independent int4 loads, then test ----
    for (unsigned base = blockIdx.x * tile + t; base < nPairs + tile; base += stride) {
        int4 p[UNB];
        bool v[UNB];
        #pragma unroll
        for (unsigned k = 0; k < UNB; k++) {
            unsigned u = base + k * 256u;
            v[k] = u < nPairs;
            if (v[k]) p[k] = __ldg(&g4[u]);
        }
        #pragma unroll
        for (unsigned k = 0; k < UNB; k++) {
            if (v[k]) {
                if (p[k].x == i) { int m = atomicAdd(&g_cnt, 1); if (m < MAX_MATCH) g_dsts[m] = p[k].y; }
                if (p[k].z == i) { int m = atomicAdd(&g_cnt, 1); if (m < MAX_MATCH) g_dsts[m] = p[k].w; }
            }
        }
        if (base >= nPairs) break;   // loop bound written to keep last partial tile simple
    }
    if (rem && blockIdx.x == 0 && t == 0) {
        int2 p = __ldg(&gall[(size_t)2 * nPairs]);   // trailing odd edge
        if (p.x == i) { int m = atomicAdd(&g_cnt, 1); if (m < MAX_MATCH) g_dsts[m] = p.y; }
    }

    // ---- grid-completion ticket (single wave: paid once, at the end) ----
    __shared__ bool s_last;
    __syncthreads();
    if (t == 0) {
        __threadfence();   // release: list writes visible before ticket
        s_last = (atomicAdd(&g_ticket, 1u) == gridDim.x - 1u);
    }
    __syncthreads();
    if (!s_last) return;

    // ================= cold epilogue: last block only =================
    __threadfence();       // acquire: see all list writes
    int cnt = *(volatile int*)&g_cnt;
    if (cnt > MAX_MATCH) cnt = MAX_MATCH;

    const int   j    = __ldg(jp);
    const float bval = __ldg(bptr);
    const int lane = t & 31;
    const int w    = t >> 5;     // 0..7

    __shared__ float sh_ssrc, sh_sdstj, sh_warp[8];

    // warps 6/7: scalar dots, concurrent with entry loads below
    if (w == 6) {
        float s = warp_dot(h + (size_t)i * D, W, D, lane);
        if (lane == 0) sh_ssrc = s;
    } else if (w == 7) {
        float s = warp_dot(h + (size_t)j * D, W + D, D, lane);
        if (lane == 0) sh_sdstj = s;
    }

    // one thread per match entry (threads 0..191), raw dot before sync
    const bool mine = (t < 192) && (t < cnt);
    float raw = 0.f;
    if (mine) raw = thread_dot(h + (size_t)g_dsts[t] * D, W + D, D);
    __syncthreads();

    const float ssrc  = sh_ssrc;
    const float sdstj = sh_sdstj;

    float v = mine ? leaky(ssrc + raw + bval) : 0.f;
    // rare overflow: entries beyond 192
    for (int m = 192 + t; m < cnt; m += 256)
        v += leaky(ssrc + thread_dot(h + (size_t)g_dsts[m] * D, W + D, D) + bval);

    // block reduction
    #pragma unroll
    for (int off = 16; off > 0; off >>= 1)
        v += __shfl_down_sync(0xffffffffu, v, off);
    if (lane == 0) sh_warp[w] = v;
    __syncthreads();

    if (t == 0) {
        float sum = 0.f;
        #pragma unroll
        for (int k = 0; k < 8; k++) sum += sh_warp[k];
        float e = leaky(ssrc + sdstj + bval);
        out[0] = e / sum;
        // reset persistent state for the next graph replay
        g_cnt = 0;
        __threadfence();
        g_ticket = 0u;
    }
}

extern "C" void kernel_launch(void* const* d_in, const int* in_sizes, int n_in,
                              void* d_out, int out_size) {
    // metadata order: g (E*2 int32), h (N*D f32), i, j, W (2D f32), b (1 f32)
    const int*   g  = (const int*)d_in[0];
    const float* h  = (const float*)d_in[1];
    const int*   ip = (const int*)d_in[2];
    const int*   jp = (const int*)d_in[3];
    const float* W  = (const float*)d_in[4];
    const float* b  = (const float*)d_in[5];
    float* out = (float*)d_out;

    long long E = (long long)in_sizes[0] / 2;
    int D = in_sizes[4] / 2;

    unsigned nPairs = (unsigned)(E / 2);   // int4 units (2 edges each)
    int rem = (int)(E & 1);

    // Single-wave persistent grid: 148 SMs x 8 blocks of 256.
    unsigned nBlocks = 148u * 8u;
    unsigned needed  = (nPairs + (256u * UNB) - 1u) / (256u * UNB);
    if (needed < nBlocks) nBlocks = needed;
    if (nBlocks < 1u) nBlocks = 1u;

    gat_fused<<<nBlocks, 256>>>((const int4*)g, nPairs, rem, (const int2*)g,
                                h, W, b, ip, jp, D, out);
}